// round 7
// baseline (speedup 1.0000x reference)
#include <cuda_runtime.h>
#include <cstdint>
#include <math.h>

#define BS 4
#define LQ 12240
#define EMBED 256
#define HEADS 8
#define MTOT (BS * LQ)   // 48960

// ---------------- scratch (no cudaMalloc allowed) ----------------
__device__ float g_v[(size_t)MTOT * 256];     // projected value [b,Lv,H,32]
__device__ float g_off[(size_t)MTOT * 256];   // offsets [b,q,H,L,P,2]
__device__ float g_attn[(size_t)MTOT * 128];  // attn logits [b,q,H,16]
__device__ float g_acc[(size_t)MTOT * 256];   // sampled acc [b,q,H,32]

// ---------------- tf32 tensor-core GEMM, paired-k smem, double buffered ----
// C[M,N] = A[M,K] @ B[K,N] + bias.  K mult of 16, N mult of 64.
// Block tile 128x64, 8 warps as 4(M) x 2(N), warp 32x32 = 2x4 m16n8k8 tiles.
// smem holds uint2 = (tf32 at k, tf32 at k+4): one LDS.64 per fragment pair.

__device__ __forceinline__ uint32_t to_tf32(float x) {
    uint32_t h;
    asm("cvt.rna.tf32.f32 %0, %1;" : "=r"(h) : "f"(x));
    return h;
}

__device__ __forceinline__ void mma_tf32(float* d, const uint32_t* a, const uint32_t* b) {
    asm volatile(
        "mma.sync.aligned.m16n8k8.row.col.f32.tf32.tf32.f32 "
        "{%0,%1,%2,%3}, {%4,%5,%6,%7}, {%8,%9}, {%0,%1,%2,%3};"
        : "+f"(d[0]), "+f"(d[1]), "+f"(d[2]), "+f"(d[3])
        : "r"(a[0]), "r"(a[1]), "r"(a[2]), "r"(a[3]), "r"(b[0]), "r"(b[1]));
}

__global__ __launch_bounds__(256) void gemm_tf32_kernel(
    const float* __restrict__ A, const float* __restrict__ B,
    const float* __restrict__ bias, float* __restrict__ C,
    int M, int N, int K)
{
    // [stage][k-pair slot][m or n]; slot s=ks*4+t holds (k=ks*8+t, k=ks*8+t+4)
    __shared__ uint2 As[2][8][133];
    __shared__ uint2 Bs[2][8][69];

    const int tid = threadIdx.x;
    const int bm = blockIdx.y * 128;
    const int bn = blockIdx.x * 64;
    const int warp = tid >> 5;
    const int lane = tid & 31;
    const int wm = (warp >> 1) * 32;
    const int wn = (warp & 1) * 32;
    const int g = lane >> 2;           // 0..7
    const int tig = lane & 3;          // 0..3

    // A fill: row = tid>>1 (0..127), half = tid&1 covers k in [half*8, half*8+8)
    const int a_row = tid >> 1;
    const int a_half = tid & 1;
    int a_grow = bm + a_row; if (a_grow >= M) a_grow = M - 1;
    const float* Ag = A + (size_t)a_grow * K + a_half * 8;

    // B fill (threads < 128): slot = t>>4 covers rows (k_lo, k_lo+4), 4 cols
    const int b_slot = (tid & 127) >> 4;           // 0..7
    const int b_klo = (b_slot >> 2) * 8 + (b_slot & 3);
    const int b_col = (tid & 15) * 4;
    const bool b_act = tid < 128;
    const float* Bg = B + (size_t)b_klo * N + bn + b_col;

    float pa0[4], pa1[4], pb0[4], pb1[4];

#define LOADG(kt) do { \
        *(float4*)pa0 = *(const float4*)(Ag + (kt) * 16); \
        *(float4*)pa1 = *(const float4*)(Ag + (kt) * 16 + 4); \
        if (b_act) { \
            *(float4*)pb0 = *(const float4*)(Bg + (size_t)(kt) * 16 * N); \
            *(float4*)pb1 = *(const float4*)(Bg + (size_t)(kt) * 16 * N + 4 * N); \
        } \
    } while (0)

#define STORES(st) do { \
        _Pragma("unroll") \
        for (int i = 0; i < 4; i++) \
            As[st][a_half * 4 + i][a_row] = make_uint2(to_tf32(pa0[i]), to_tf32(pa1[i])); \
        if (b_act) { \
            _Pragma("unroll") \
            for (int i = 0; i < 4; i++) \
                Bs[st][b_slot][b_col + i] = make_uint2(to_tf32(pb0[i]), to_tf32(pb1[i])); \
        } \
    } while (0)

    float acc[2][4][4];
#pragma unroll
    for (int i = 0; i < 2; i++)
#pragma unroll
        for (int j = 0; j < 4; j++)
#pragma unroll
            for (int r = 0; r < 4; r++) acc[i][j][r] = 0.f;

    const int NT = K / 16;
    LOADG(0);
    STORES(0);
    __syncthreads();

    int st = 0;
    for (int kt = 0; kt < NT; kt++) {
        if (kt + 1 < NT) LOADG(kt + 1);

#pragma unroll
        for (int ks = 0; ks < 2; ks++) {
            const int kp = ks * 4 + tig;
            uint32_t af[2][4];
#pragma unroll
            for (int mt = 0; mt < 2; mt++) {
                const int mb = wm + mt * 16;
                uint2 u0 = As[st][kp][mb + g];
                uint2 u1 = As[st][kp][mb + g + 8];
                af[mt][0] = u0.x; af[mt][1] = u1.x;
                af[mt][2] = u0.y; af[mt][3] = u1.y;
            }
            uint32_t bf[4][2];
#pragma unroll
            for (int nt = 0; nt < 4; nt++) {
                uint2 ub = Bs[st][kp][wn + nt * 8 + g];
                bf[nt][0] = ub.x; bf[nt][1] = ub.y;
            }
#pragma unroll
            for (int mt = 0; mt < 2; mt++)
#pragma unroll
                for (int nt = 0; nt < 4; nt++)
                    mma_tf32(acc[mt][nt], af[mt], bf[nt]);
        }

        if (kt + 1 < NT) STORES(st ^ 1);
        st ^= 1;
        __syncthreads();
    }

    // epilogue: D + bias -> C
#pragma unroll
    for (int nt = 0; nt < 4; nt++) {
        const int n = bn + wn + nt * 8 + 2 * tig;
        const float b0 = bias[n];
        const float b1 = bias[n + 1];
#pragma unroll
        for (int mt = 0; mt < 2; mt++) {
            const int m0 = bm + wm + mt * 16 + g;
            if (m0 < M) {
                float2 o = make_float2(acc[mt][nt][0] + b0, acc[mt][nt][1] + b1);
                *(float2*)&C[(size_t)m0 * N + n] = o;
            }
            const int m1 = m0 + 8;
            if (m1 < M) {
                float2 o = make_float2(acc[mt][nt][2] + b0, acc[mt][nt][3] + b1);
                *(float2*)&C[(size_t)m1 * N + n] = o;
            }
        }
    }
#undef LOADG
#undef STORES
}

// ---------------- softmax + bilinear sampling ----------------
__global__ __launch_bounds__(256) void sample_kernel(
    const float* __restrict__ refp,   // [BS,LQ,4,2]
    const float* __restrict__ off,    // [BS*LQ, 256] = [H][L][P][2]
    const float* __restrict__ logits, // [BS*LQ, 128] = [H][16]
    const float* __restrict__ v,      // [BS,LQ,8,32]
    float* __restrict__ out)          // [BS*LQ, 256]
{
    __shared__ int4   s_off[HEADS][16];
    __shared__ float4 s_w[HEADS][16];

    const int bq = blockIdx.x;
    const int b = bq / LQ;
    const int h = threadIdx.x >> 5;
    const int lane = threadIdx.x & 31;
    const int j = lane & 15;          // (level,point) index

    const float* lg = logits + (size_t)bq * 128 + h * 16;
    float logit = lg[j];
    float mx = logit;
#pragma unroll
    for (int k = 8; k >= 1; k >>= 1)
        mx = fmaxf(mx, __shfl_xor_sync(0xffffffffu, mx, k, 16));
    float e = __expf(logit - mx);
    float s = e;
#pragma unroll
    for (int k = 8; k >= 1; k >>= 1)
        s += __shfl_xor_sync(0xffffffffu, s, k, 16);
    const float aw = e / s;

    const int l = j >> 2;
    const int D = 96 >> l;
    const int start = 12288 - (12288 >> (2 * l));
    const float fD = (float)D;

    const float2 r2 = ((const float2*)(refp + (size_t)bq * 8))[l];
    const float2 o2 = ((const float2*)(off + (size_t)bq * 256 + h * 32))[j];

    const float gx = fmaf(r2.x, fD, o2.x) - 0.5f;
    const float gy = fmaf(r2.y, fD, o2.y) - 0.5f;
    const float x0f = floorf(gx);
    const float y0f = floorf(gy);
    const float wx = gx - x0f;
    const float wy = gy - y0f;
    const int x0 = (int)x0f, y0 = (int)y0f;
    const int x1 = x0 + 1, y1 = y0 + 1;

    const bool vx0 = (x0 >= 0) & (x0 < D);
    const bool vx1 = (x1 >= 0) & (x1 < D);
    const bool vy0 = (y0 >= 0) & (y0 < D);
    const bool vy1 = (y1 >= 0) & (y1 < D);

    int4 o4;
    float4 w4;
    o4.x = (vx0 & vy0) ? (start + y0 * D + x0) * 256 : 0;
    o4.y = (vx1 & vy0) ? (start + y0 * D + x1) * 256 : 0;
    o4.z = (vx0 & vy1) ? (start + y1 * D + x0) * 256 : 0;
    o4.w = (vx1 & vy1) ? (start + y1 * D + x1) * 256 : 0;
    w4.x = (vx0 & vy0) ? (1.f - wx) * (1.f - wy) * aw : 0.f;
    w4.y = (vx1 & vy0) ? wx * (1.f - wy) * aw : 0.f;
    w4.z = (vx0 & vy1) ? (1.f - wx) * wy * aw : 0.f;
    w4.w = (vx1 & vy1) ? wx * wy * aw : 0.f;

    if (lane < 16) {
        s_off[h][j] = o4;
        s_w[h][j] = w4;
    }
    __syncwarp();

    const float* __restrict__ vb = v + (size_t)b * LQ * 256 + h * 32 + lane;
    float acc = 0.f;
#pragma unroll
    for (int p = 0; p < 16; p++) {
        const int4 o = s_off[h][p];
        const float4 w = s_w[h][p];
        acc = fmaf(w.x, __ldg(vb + o.x), acc);
        acc = fmaf(w.y, __ldg(vb + o.y), acc);
        acc = fmaf(w.z, __ldg(vb + o.z), acc);
        acc = fmaf(w.w, __ldg(vb + o.w), acc);
    }
    out[(size_t)bq * 256 + h * 32 + lane] = acc;
}

// ---------------- launch ----------------
extern "C" void kernel_launch(void* const* d_in, const int* in_sizes, int n_in,
                              void* d_out, int out_size)
{
    const float* query = (const float*)d_in[0];
    const float* refp  = (const float*)d_in[1];
    const float* value = (const float*)d_in[2];
    // d_in[3] = value_spatial_shapes (static, hardcoded)
    const float* W_off  = (const float*)d_in[4];
    const float* b_off  = (const float*)d_in[5];
    const float* W_attn = (const float*)d_in[6];
    const float* b_attn = (const float*)d_in[7];
    const float* W_val  = (const float*)d_in[8];
    const float* b_val  = (const float*)d_in[9];
    const float* W_out  = (const float*)d_in[10];
    const float* b_out  = (const float*)d_in[11];
    float* out = (float*)d_out;

    float *pv, *poff, *pattn, *pacc;
    cudaGetSymbolAddress((void**)&pv, g_v);
    cudaGetSymbolAddress((void**)&poff, g_off);
    cudaGetSymbolAddress((void**)&pattn, g_attn);
    cudaGetSymbolAddress((void**)&pacc, g_acc);

    const int M = MTOT;
    dim3 blk(256);
    dim3 grid256(256 / 64, (M + 127) / 128);
    dim3 grid128(128 / 64, (M + 127) / 128);

    gemm_tf32_kernel<<<grid256, blk>>>(value, W_val, b_val, pv, M, 256, 256);
    gemm_tf32_kernel<<<grid256, blk>>>(query, W_off, b_off, poff, M, 256, 256);
    gemm_tf32_kernel<<<grid128, blk>>>(query, W_attn, b_attn, pattn, M, 128, 256);
    sample_kernel<<<M, blk>>>(refp, poff, pattn, pv, pacc);
    gemm_tf32_kernel<<<grid256, blk>>>(pacc, W_out, b_out, out, M, 256, 256);
}

// round 8
// speedup vs baseline: 1.1816x; 1.1816x over previous
#include <cuda_runtime.h>
#include <cstdint>
#include <math.h>

#define BS 4
#define LQ 12240
#define EMBED 256
#define HEADS 8
#define MTOT (BS * LQ)   // 48960

// ---------------- scratch (no cudaMalloc allowed) ----------------
__device__ float g_v[(size_t)MTOT * 256];     // projected value [b,Lv,H,32]
__device__ float g_off[(size_t)MTOT * 256];   // offsets [b,q,H,L,P,2]
__device__ float g_attn[(size_t)MTOT * 128];  // attn logits [b,q,H,16]
__device__ float g_acc[(size_t)MTOT * 256];   // sampled acc [b,q,H,32]

// ---------------- tf32 tensor-core GEMM, paired-k smem, single buffered ----
// C[M,N] = A[M,K] @ B[K,N] + bias.  K mult of 16, N mult of 64.
// Block tile 128x64, 8 warps as 4(M) x 2(N), warp 32x32 = 2x4 m16n8k8 tiles.
// smem element = uint2 (tf32 at k, tf32 at k+4): one LDS.64 per fragment pair.
// Slot s (0..7) holds k-pair (k_lo, k_lo+4) with k_lo = (s>>2)*8 + (s&3).

__device__ __forceinline__ uint32_t to_tf32(float x) {
    uint32_t h;
    asm("cvt.rna.tf32.f32 %0, %1;" : "=r"(h) : "f"(x));
    return h;
}

__device__ __forceinline__ void mma_tf32(float* d, const uint32_t* a, const uint32_t* b) {
    asm volatile(
        "mma.sync.aligned.m16n8k8.row.col.f32.tf32.tf32.f32 "
        "{%0,%1,%2,%3}, {%4,%5,%6,%7}, {%8,%9}, {%0,%1,%2,%3};"
        : "+f"(d[0]), "+f"(d[1]), "+f"(d[2]), "+f"(d[3])
        : "r"(a[0]), "r"(a[1]), "r"(a[2]), "r"(a[3]), "r"(b[0]), "r"(b[1]));
}

__global__ __launch_bounds__(256) void gemm_tf32_kernel(
    const float* __restrict__ A, const float* __restrict__ B,
    const float* __restrict__ bias, float* __restrict__ C,
    int M, int N, int K)
{
    __shared__ uint2 As[8][132];   // [slot][m]
    __shared__ uint2 Bs[8][68];    // [slot][n]

    const int tid = threadIdx.x;
    const int bm = blockIdx.y * 128;
    const int bn = blockIdx.x * 64;
    const int warp = tid >> 5;
    const int lane = tid & 31;
    const int wm = (warp >> 1) * 32;
    const int wn = (warp & 1) * 32;
    const int g = lane >> 2;           // 0..7
    const int tig = lane & 3;          // 0..3

    // A fill: row = tid>>1 (0..127), half = tid&1 -> k base half*8
    const int a_row = tid >> 1;
    const int a_half = tid & 1;
    int a_grow = bm + a_row; if (a_grow >= M) a_grow = M - 1;
    const float* Ag = A + (size_t)a_grow * K + a_half * 8;

    // B fill: col = tid&63, s = tid>>6 (0..3); loads B[s],[s+4],[s+8],[s+12] at col
    const int b_col = tid & 63;
    const int b_s = tid >> 6;
    const float* Bg = B + (size_t)b_s * N + bn + b_col;

    float acc[2][4][4];
#pragma unroll
    for (int i = 0; i < 2; i++)
#pragma unroll
        for (int j = 0; j < 4; j++)
#pragma unroll
            for (int r = 0; r < 4; r++) acc[i][j][r] = 0.f;

    for (int kt = 0; kt < K / 16; kt++) {
        // ---- fill A: two float4 (k=half*8..+3, +4..+7) -> 4 uint2 ----
        {
            const float* ap = Ag + kt * 16;
            float4 a0 = *(const float4*)ap;
            float4 a1 = *(const float4*)(ap + 4);
            const int sb = a_half * 4;
            As[sb + 0][a_row] = make_uint2(to_tf32(a0.x), to_tf32(a1.x));
            As[sb + 1][a_row] = make_uint2(to_tf32(a0.y), to_tf32(a1.y));
            As[sb + 2][a_row] = make_uint2(to_tf32(a0.z), to_tf32(a1.z));
            As[sb + 3][a_row] = make_uint2(to_tf32(a0.w), to_tf32(a1.w));
        }
        // ---- fill B: 4 coalesced scalar streams ----
        {
            const float* bp = Bg + (size_t)kt * 16 * N;
            float v0 = bp[0];
            float v4 = bp[4 * (size_t)N];
            float v8 = bp[8 * (size_t)N];
            float v12 = bp[12 * (size_t)N];
            Bs[b_s][b_col]     = make_uint2(to_tf32(v0), to_tf32(v4));
            Bs[b_s + 4][b_col] = make_uint2(to_tf32(v8), to_tf32(v12));
        }
        __syncthreads();

#pragma unroll
        for (int ks = 0; ks < 2; ks++) {
            const int kp = ks * 4 + tig;
            uint32_t af[2][4];
#pragma unroll
            for (int mt = 0; mt < 2; mt++) {
                const int mb = wm + mt * 16;
                uint2 u0 = As[kp][mb + g];
                uint2 u1 = As[kp][mb + g + 8];
                af[mt][0] = u0.x; af[mt][1] = u1.x;
                af[mt][2] = u0.y; af[mt][3] = u1.y;
            }
            uint32_t bf[4][2];
#pragma unroll
            for (int nt = 0; nt < 4; nt++) {
                uint2 ub = Bs[kp][wn + nt * 8 + g];
                bf[nt][0] = ub.x; bf[nt][1] = ub.y;
            }
#pragma unroll
            for (int mt = 0; mt < 2; mt++)
#pragma unroll
                for (int nt = 0; nt < 4; nt++)
                    mma_tf32(acc[mt][nt], af[mt], bf[nt]);
        }
        __syncthreads();
    }

    // epilogue: D + bias -> C
#pragma unroll
    for (int nt = 0; nt < 4; nt++) {
        const int n = bn + wn + nt * 8 + 2 * tig;
        const float b0 = bias[n];
        const float b1 = bias[n + 1];
#pragma unroll
        for (int mt = 0; mt < 2; mt++) {
            const int m0 = bm + wm + mt * 16 + g;
            if (m0 < M) {
                float2 o = make_float2(acc[mt][nt][0] + b0, acc[mt][nt][1] + b1);
                *(float2*)&C[(size_t)m0 * N + n] = o;
            }
            const int m1 = m0 + 8;
            if (m1 < M) {
                float2 o = make_float2(acc[mt][nt][2] + b0, acc[mt][nt][3] + b1);
                *(float2*)&C[(size_t)m1 * N + n] = o;
            }
        }
    }
}

// ---------------- softmax + bilinear sampling ----------------
__global__ __launch_bounds__(256) void sample_kernel(
    const float* __restrict__ refp,   // [BS,LQ,4,2]
    const float* __restrict__ off,    // [BS*LQ, 256] = [H][L][P][2]
    const float* __restrict__ logits, // [BS*LQ, 128] = [H][16]
    const float* __restrict__ v,      // [BS,LQ,8,32]
    float* __restrict__ out)          // [BS*LQ, 256]
{
    __shared__ int4   s_off[HEADS][16];
    __shared__ float4 s_w[HEADS][16];

    const int bq = blockIdx.x;
    const int b = bq / LQ;
    const int h = threadIdx.x >> 5;
    const int lane = threadIdx.x & 31;
    const int j = lane & 15;          // (level,point) index

    const float* lg = logits + (size_t)bq * 128 + h * 16;
    float logit = lg[j];
    float mx = logit;
#pragma unroll
    for (int k = 8; k >= 1; k >>= 1)
        mx = fmaxf(mx, __shfl_xor_sync(0xffffffffu, mx, k, 16));
    float e = __expf(logit - mx);
    float s = e;
#pragma unroll
    for (int k = 8; k >= 1; k >>= 1)
        s += __shfl_xor_sync(0xffffffffu, s, k, 16);
    const float aw = e / s;

    const int l = j >> 2;
    const int D = 96 >> l;
    const int start = 12288 - (12288 >> (2 * l));
    const float fD = (float)D;

    const float2 r2 = ((const float2*)(refp + (size_t)bq * 8))[l];
    const float2 o2 = ((const float2*)(off + (size_t)bq * 256 + h * 32))[j];

    const float gx = fmaf(r2.x, fD, o2.x) - 0.5f;
    const float gy = fmaf(r2.y, fD, o2.y) - 0.5f;
    const float x0f = floorf(gx);
    const float y0f = floorf(gy);
    const float wx = gx - x0f;
    const float wy = gy - y0f;
    const int x0 = (int)x0f, y0 = (int)y0f;
    const int x1 = x0 + 1, y1 = y0 + 1;

    const bool vx0 = (x0 >= 0) & (x0 < D);
    const bool vx1 = (x1 >= 0) & (x1 < D);
    const bool vy0 = (y0 >= 0) & (y0 < D);
    const bool vy1 = (y1 >= 0) & (y1 < D);

    int4 o4;
    float4 w4;
    o4.x = (vx0 & vy0) ? (start + y0 * D + x0) * 256 : 0;
    o4.y = (vx1 & vy0) ? (start + y0 * D + x1) * 256 : 0;
    o4.z = (vx0 & vy1) ? (start + y1 * D + x0) * 256 : 0;
    o4.w = (vx1 & vy1) ? (start + y1 * D + x1) * 256 : 0;
    w4.x = (vx0 & vy0) ? (1.f - wx) * (1.f - wy) * aw : 0.f;
    w4.y = (vx1 & vy0) ? wx * (1.f - wy) * aw : 0.f;
    w4.z = (vx0 & vy1) ? (1.f - wx) * wy * aw : 0.f;
    w4.w = (vx1 & vy1) ? wx * wy * aw : 0.f;

    if (lane < 16) {
        s_off[h][j] = o4;
        s_w[h][j] = w4;
    }
    __syncwarp();

    const float* __restrict__ vb = v + (size_t)b * LQ * 256 + h * 32 + lane;
    float acc = 0.f;
#pragma unroll
    for (int p = 0; p < 16; p++) {
        const int4 o = s_off[h][p];
        const float4 w = s_w[h][p];
        acc = fmaf(w.x, __ldg(vb + o.x), acc);
        acc = fmaf(w.y, __ldg(vb + o.y), acc);
        acc = fmaf(w.z, __ldg(vb + o.z), acc);
        acc = fmaf(w.w, __ldg(vb + o.w), acc);
    }
    out[(size_t)bq * 256 + h * 32 + lane] = acc;
}

// ---------------- launch ----------------
extern "C" void kernel_launch(void* const* d_in, const int* in_sizes, int n_in,
                              void* d_out, int out_size)
{
    const float* query = (const float*)d_in[0];
    const float* refp  = (const float*)d_in[1];
    const float* value = (const float*)d_in[2];
    // d_in[3] = value_spatial_shapes (static, hardcoded)
    const float* W_off  = (const float*)d_in[4];
    const float* b_off  = (const float*)d_in[5];
    const float* W_attn = (const float*)d_in[6];
    const float* b_attn = (const float*)d_in[7];
    const float* W_val  = (const float*)d_in[8];
    const float* b_val  = (const float*)d_in[9];
    const float* W_out  = (const float*)d_in[10];
    const float* b_out  = (const float*)d_in[11];
    float* out = (float*)d_out;

    float *pv, *poff, *pattn, *pacc;
    cudaGetSymbolAddress((void**)&pv, g_v);
    cudaGetSymbolAddress((void**)&poff, g_off);
    cudaGetSymbolAddress((void**)&pattn, g_attn);
    cudaGetSymbolAddress((void**)&pacc, g_acc);

    const int M = MTOT;
    dim3 blk(256);
    dim3 grid256(256 / 64, (M + 127) / 128);
    dim3 grid128(128 / 64, (M + 127) / 128);

    gemm_tf32_kernel<<<grid256, blk>>>(value, W_val, b_val, pv, M, 256, 256);
    gemm_tf32_kernel<<<grid256, blk>>>(query, W_off, b_off, poff, M, 256, 256);
    gemm_tf32_kernel<<<grid128, blk>>>(query, W_attn, b_attn, pattn, M, 128, 256);
    sample_kernel<<<M, blk>>>(refp, poff, pattn, pv, pacc);
    gemm_tf32_kernel<<<grid256, blk>>>(pacc, W_out, b_out, out, M, 256, 256);
}

// round 9
// speedup vs baseline: 1.2637x; 1.0694x over previous
#include <cuda_runtime.h>
#include <cstdint>
#include <math.h>

#define BS 4
#define LQ 12240
#define EMBED 256
#define HEADS 8
#define MTOT (BS * LQ)   // 48960

// ---------------- scratch (no cudaMalloc allowed) ----------------
__device__ float g_v[(size_t)MTOT * 256];     // projected value [b,Lv,H,32]
__device__ float g_off[(size_t)MTOT * 256];   // offsets [b,q,H,L,P,2]
__device__ float g_attn[(size_t)MTOT * 128];  // attn logits [b,q,H,16]
__device__ float g_acc[(size_t)MTOT * 256];   // sampled acc [b,q,H,32]

// ---------------- tf32 tensor-core GEMM, paired-k smem, 128x128 tile ------
// C[M,N] = A[M,K] @ B[K,N] + bias.  K mult of 16, N mult of 128.
// Block tile 128x128, 8 warps as 4(M) x 2(N), warp 32x64 = 2x8 m16n8k8 tiles.
// smem element = uint2 (tf32 at k, tf32 at k+4): one LDS.64 per fragment pair.
// Slot s (0..7) holds k-pair (k_lo, k_lo+4) with k_lo = (s>>2)*8 + (s&3).

__device__ __forceinline__ uint32_t to_tf32(float x) {
    uint32_t h;
    asm("cvt.rna.tf32.f32 %0, %1;" : "=r"(h) : "f"(x));
    return h;
}

__device__ __forceinline__ void mma_tf32(float* d, const uint32_t* a, const uint32_t* b) {
    asm volatile(
        "mma.sync.aligned.m16n8k8.row.col.f32.tf32.tf32.f32 "
        "{%0,%1,%2,%3}, {%4,%5,%6,%7}, {%8,%9}, {%0,%1,%2,%3};"
        : "+f"(d[0]), "+f"(d[1]), "+f"(d[2]), "+f"(d[3])
        : "r"(a[0]), "r"(a[1]), "r"(a[2]), "r"(a[3]), "r"(b[0]), "r"(b[1]));
}

__global__ __launch_bounds__(256) void gemm_tf32_kernel(
    const float* __restrict__ A, const float* __restrict__ B,
    const float* __restrict__ bias, float* __restrict__ C,
    int M, int N, int K)
{
    __shared__ uint2 As[8][132];   // [slot][m]
    __shared__ uint2 Bs[8][132];   // [slot][n]

    const int tid = threadIdx.x;
    const int bm = blockIdx.y * 128;
    const int bn = blockIdx.x * 128;
    const int warp = tid >> 5;
    const int lane = tid & 31;
    const int wm = (warp >> 1) * 32;
    const int wn = (warp & 1) * 64;
    const int g = lane >> 2;           // 0..7
    const int tig = lane & 3;          // 0..3

    // A fill: row = tid>>1 (0..127), half = tid&1 -> k base half*8
    const int a_row = tid >> 1;
    const int a_half = tid & 1;
    int a_grow = bm + a_row; if (a_grow >= M) a_grow = M - 1;
    const float* Ag = A + (size_t)a_grow * K + a_half * 8;

    // B fill: col = tid&127, group t = tid>>7 (0..1) handles slots 4t..4t+3
    const int b_col = tid & 127;
    const int b_t = tid >> 7;
    const float* Bg = B + bn + b_col + (size_t)(8 * b_t) * N;

    float acc[2][8][4];
#pragma unroll
    for (int i = 0; i < 2; i++)
#pragma unroll
        for (int j = 0; j < 8; j++)
#pragma unroll
            for (int r = 0; r < 4; r++) acc[i][j][r] = 0.f;

    for (int kt = 0; kt < K / 16; kt++) {
        // ---- fill A: two float4 (k=half*8..+3, +4..+7) -> 4 uint2 ----
        {
            const float* ap = Ag + kt * 16;
            float4 a0 = *(const float4*)ap;
            float4 a1 = *(const float4*)(ap + 4);
            const int sb = a_half * 4;
            As[sb + 0][a_row] = make_uint2(to_tf32(a0.x), to_tf32(a1.x));
            As[sb + 1][a_row] = make_uint2(to_tf32(a0.y), to_tf32(a1.y));
            As[sb + 2][a_row] = make_uint2(to_tf32(a0.z), to_tf32(a1.z));
            As[sb + 3][a_row] = make_uint2(to_tf32(a0.w), to_tf32(a1.w));
        }
        // ---- fill B: 8 coalesced scalar streams -> 4 uint2 ----
        {
            const float* bp = Bg + (size_t)kt * 16 * N;
#pragma unroll
            for (int i = 0; i < 4; i++) {
                float v0 = bp[(size_t)i * N];
                float v1 = bp[(size_t)(i + 4) * N];
                Bs[4 * b_t + i][b_col] = make_uint2(to_tf32(v0), to_tf32(v1));
            }
        }
        __syncthreads();

#pragma unroll
        for (int ks = 0; ks < 2; ks++) {
            const int kp = ks * 4 + tig;
            uint32_t af[2][4];
#pragma unroll
            for (int mt = 0; mt < 2; mt++) {
                const int mb = wm + mt * 16;
                uint2 u0 = As[kp][mb + g];
                uint2 u1 = As[kp][mb + g + 8];
                af[mt][0] = u0.x; af[mt][1] = u1.x;
                af[mt][2] = u0.y; af[mt][3] = u1.y;
            }
            uint32_t bf[8][2];
#pragma unroll
            for (int nt = 0; nt < 8; nt++) {
                uint2 ub = Bs[kp][wn + nt * 8 + g];
                bf[nt][0] = ub.x; bf[nt][1] = ub.y;
            }
#pragma unroll
            for (int mt = 0; mt < 2; mt++)
#pragma unroll
                for (int nt = 0; nt < 8; nt++)
                    mma_tf32(acc[mt][nt], af[mt], bf[nt]);
        }
        __syncthreads();
    }

    // epilogue: D + bias -> C
#pragma unroll
    for (int nt = 0; nt < 8; nt++) {
        const int n = bn + wn + nt * 8 + 2 * tig;
        const float b0 = bias[n];
        const float b1 = bias[n + 1];
#pragma unroll
        for (int mt = 0; mt < 2; mt++) {
            const int m0 = bm + wm + mt * 16 + g;
            if (m0 < M) {
                float2 o = make_float2(acc[mt][nt][0] + b0, acc[mt][nt][1] + b1);
                *(float2*)&C[(size_t)m0 * N + n] = o;
            }
            const int m1 = m0 + 8;
            if (m1 < M) {
                float2 o = make_float2(acc[mt][nt][2] + b0, acc[mt][nt][3] + b1);
                *(float2*)&C[(size_t)m1 * N + n] = o;
            }
        }
    }
}

// ---------------- softmax + bilinear sampling ----------------
__global__ __launch_bounds__(256) void sample_kernel(
    const float* __restrict__ refp,   // [BS,LQ,4,2]
    const float* __restrict__ off,    // [BS*LQ, 256] = [H][L][P][2]
    const float* __restrict__ logits, // [BS*LQ, 128] = [H][16]
    const float* __restrict__ v,      // [BS,LQ,8,32]
    float* __restrict__ out)          // [BS*LQ, 256]
{
    __shared__ int4   s_off[HEADS][16];
    __shared__ float4 s_w[HEADS][16];

    const int bq = blockIdx.x;
    const int b = bq / LQ;
    const int h = threadIdx.x >> 5;
    const int lane = threadIdx.x & 31;
    const int j = lane & 15;          // (level,point) index

    const float* lg = logits + (size_t)bq * 128 + h * 16;
    float logit = lg[j];
    float mx = logit;
#pragma unroll
    for (int k = 8; k >= 1; k >>= 1)
        mx = fmaxf(mx, __shfl_xor_sync(0xffffffffu, mx, k, 16));
    float e = __expf(logit - mx);
    float s = e;
#pragma unroll
    for (int k = 8; k >= 1; k >>= 1)
        s += __shfl_xor_sync(0xffffffffu, s, k, 16);
    const float aw = e / s;

    const int l = j >> 2;
    const int D = 96 >> l;
    const int start = 12288 - (12288 >> (2 * l));
    const float fD = (float)D;

    const float2 r2 = ((const float2*)(refp + (size_t)bq * 8))[l];
    const float2 o2 = ((const float2*)(off + (size_t)bq * 256 + h * 32))[j];

    const float gx = fmaf(r2.x, fD, o2.x) - 0.5f;
    const float gy = fmaf(r2.y, fD, o2.y) - 0.5f;
    const float x0f = floorf(gx);
    const float y0f = floorf(gy);
    const float wx = gx - x0f;
    const float wy = gy - y0f;
    const int x0 = (int)x0f, y0 = (int)y0f;
    const int x1 = x0 + 1, y1 = y0 + 1;

    const bool vx0 = (x0 >= 0) & (x0 < D);
    const bool vx1 = (x1 >= 0) & (x1 < D);
    const bool vy0 = (y0 >= 0) & (y0 < D);
    const bool vy1 = (y1 >= 0) & (y1 < D);

    int4 o4;
    float4 w4;
    o4.x = (vx0 & vy0) ? (start + y0 * D + x0) * 256 : 0;
    o4.y = (vx1 & vy0) ? (start + y0 * D + x1) * 256 : 0;
    o4.z = (vx0 & vy1) ? (start + y1 * D + x0) * 256 : 0;
    o4.w = (vx1 & vy1) ? (start + y1 * D + x1) * 256 : 0;
    w4.x = (vx0 & vy0) ? (1.f - wx) * (1.f - wy) * aw : 0.f;
    w4.y = (vx1 & vy0) ? wx * (1.f - wy) * aw : 0.f;
    w4.z = (vx0 & vy1) ? (1.f - wx) * wy * aw : 0.f;
    w4.w = (vx1 & vy1) ? wx * wy * aw : 0.f;

    if (lane < 16) {
        s_off[h][j] = o4;
        s_w[h][j] = w4;
    }
    __syncwarp();

    const float* __restrict__ vb = v + (size_t)b * LQ * 256 + h * 32 + lane;
    float acc = 0.f;
#pragma unroll
    for (int p = 0; p < 16; p++) {
        const int4 o = s_off[h][p];
        const float4 w = s_w[h][p];
        acc = fmaf(w.x, __ldg(vb + o.x), acc);
        acc = fmaf(w.y, __ldg(vb + o.y), acc);
        acc = fmaf(w.z, __ldg(vb + o.z), acc);
        acc = fmaf(w.w, __ldg(vb + o.w), acc);
    }
    out[(size_t)bq * 256 + h * 32 + lane] = acc;
}

// ---------------- launch ----------------
extern "C" void kernel_launch(void* const* d_in, const int* in_sizes, int n_in,
                              void* d_out, int out_size)
{
    const float* query = (const float*)d_in[0];
    const float* refp  = (const float*)d_in[1];
    const float* value = (const float*)d_in[2];
    // d_in[3] = value_spatial_shapes (static, hardcoded)
    const float* W_off  = (const float*)d_in[4];
    const float* b_off  = (const float*)d_in[5];
    const float* W_attn = (const float*)d_in[6];
    const float* b_attn = (const float*)d_in[7];
    const float* W_val  = (const float*)d_in[8];
    const float* b_val  = (const float*)d_in[9];
    const float* W_out  = (const float*)d_in[10];
    const float* b_out  = (const float*)d_in[11];
    float* out = (float*)d_out;

    float *pv, *poff, *pattn, *pacc;
    cudaGetSymbolAddress((void**)&pv, g_v);
    cudaGetSymbolAddress((void**)&poff, g_off);
    cudaGetSymbolAddress((void**)&pattn, g_attn);
    cudaGetSymbolAddress((void**)&pacc, g_acc);

    const int M = MTOT;
    dim3 blk(256);
    dim3 grid256(2, (M + 127) / 128);
    dim3 grid128(1, (M + 127) / 128);

    gemm_tf32_kernel<<<grid256, blk>>>(value, W_val, b_val, pv, M, 256, 256);
    gemm_tf32_kernel<<<grid256, blk>>>(query, W_off, b_off, poff, M, 256, 256);
    gemm_tf32_kernel<<<grid128, blk>>>(query, W_attn, b_attn, pattn, M, 128, 256);
    sample_kernel<<<M, blk>>>(refp, poff, pattn, pv, pacc);
    gemm_tf32_kernel<<<grid256, blk>>>(pacc, W_out, b_out, out, M, 256, 256);
}

// round 10
// speedup vs baseline: 1.3493x; 1.0677x over previous
#include <cuda_runtime.h>
#include <cstdint>
#include <math.h>

#define BS 4
#define LQ 12240
#define EMBED 256
#define HEADS 8
#define MTOT (BS * LQ)   // 48960

// ---------------- scratch (no cudaMalloc allowed) ----------------
__device__ float g_v[(size_t)MTOT * 256];     // projected value [b,Lv,H,32]
__device__ float g_off[(size_t)MTOT * 256];   // offsets [b,q,H,L,P,2]
__device__ float g_attn[(size_t)MTOT * 128];  // attn logits [b,q,H,16]
__device__ float g_acc[(size_t)MTOT * 256];   // sampled acc [b,q,H,32]

// ---------------- tf32 tensor-core GEMM, cp.async 2-stage pipeline --------
// C[M,N] = A[M,K] @ B[K,N] + bias.  K mult of 16, N mult of 128 (or =128).
// Block tile 128x128, 8 warps as 4(M) x 2(N), warp 32x64 = 2x8 m16n8k8 tiles.
// smem holds raw fp32 (filled by cp.async); cvt to tf32 at fragment load.

__device__ __forceinline__ uint32_t to_tf32(float x) {
    uint32_t h;
    asm("cvt.rna.tf32.f32 %0, %1;" : "=r"(h) : "f"(x));
    return h;
}

__device__ __forceinline__ void mma_tf32(float* d, const uint32_t* a, const uint32_t* b) {
    asm volatile(
        "mma.sync.aligned.m16n8k8.row.col.f32.tf32.tf32.f32 "
        "{%0,%1,%2,%3}, {%4,%5,%6,%7}, {%8,%9}, {%0,%1,%2,%3};"
        : "+f"(d[0]), "+f"(d[1]), "+f"(d[2]), "+f"(d[3])
        : "r"(a[0]), "r"(a[1]), "r"(a[2]), "r"(a[3]), "r"(b[0]), "r"(b[1]));
}

__device__ __forceinline__ void cp_async16(void* smem, const void* gmem) {
    uint32_t s = (uint32_t)__cvta_generic_to_shared(smem);
    asm volatile("cp.async.ca.shared.global [%0], [%1], 16;" :: "r"(s), "l"(gmem));
}

#define ASTRIDE 20    // floats per A row (16 + 4 pad) -> conflict-free frag LDS
#define BSTRIDE 136   // floats per B row (128 + 8 pad) -> conflict-free frag LDS

__global__ __launch_bounds__(256) void gemm_tf32_kernel(
    const float* __restrict__ A, const float* __restrict__ B,
    const float* __restrict__ bias, float* __restrict__ C,
    int M, int N, int K)
{
    __shared__ float As[2][128][ASTRIDE];
    __shared__ float Bs[2][16][BSTRIDE];

    const int tid = threadIdx.x;
    const int bm = blockIdx.y * 128;
    const int bn = blockIdx.x * 128;
    const int warp = tid >> 5;
    const int lane = tid & 31;
    const int wm = (warp >> 1) * 32;
    const int wn = (warp & 1) * 64;
    const int g = lane >> 2;           // 0..7
    const int tig = lane & 3;          // 0..3

    // A fill: thread copies 32B of row (tid>>1) at k-offset (tid&1)*8
    const int a_row = tid >> 1;
    const int a_half = tid & 1;
    int a_grow = bm + a_row; if (a_grow >= M) a_grow = M - 1;
    const float* Ag = A + (size_t)a_grow * K + a_half * 8;

    // B fill: thread copies 32B of tile-row (tid>>4) at col (tid&15)*8
    const int b_row = tid >> 4;          // 0..15
    const int b_col = (tid & 15) * 8;    // 0..120
    const float* Bg = B + (size_t)b_row * N + bn + b_col;

#define FILL(kt, st) do { \
        const float* ap = Ag + (kt) * 16; \
        cp_async16(&As[st][a_row][a_half * 8], ap); \
        cp_async16(&As[st][a_row][a_half * 8 + 4], ap + 4); \
        const float* bp = Bg + (size_t)(kt) * 16 * N; \
        cp_async16(&Bs[st][b_row][b_col], bp); \
        cp_async16(&Bs[st][b_row][b_col + 4], bp + 4); \
        asm volatile("cp.async.commit_group;"); \
    } while (0)

    float acc[2][8][4];
#pragma unroll
    for (int i = 0; i < 2; i++)
#pragma unroll
        for (int j = 0; j < 8; j++)
#pragma unroll
            for (int r = 0; r < 4; r++) acc[i][j][r] = 0.f;

    const int NT = K / 16;
    FILL(0, 0);

    int st = 0;
    for (int kt = 0; kt < NT; kt++) {
        if (kt + 1 < NT) {
            FILL(kt + 1, st ^ 1);
            asm volatile("cp.async.wait_group 1;");
        } else {
            asm volatile("cp.async.wait_group 0;");
        }
        __syncthreads();

#pragma unroll
        for (int ks = 0; ks < 2; ks++) {
            const int k8 = ks * 8;
            uint32_t af[2][4];
#pragma unroll
            for (int mt = 0; mt < 2; mt++) {
                const int mb = wm + mt * 16;
                af[mt][0] = to_tf32(As[st][mb + g][k8 + tig]);
                af[mt][1] = to_tf32(As[st][mb + g + 8][k8 + tig]);
                af[mt][2] = to_tf32(As[st][mb + g][k8 + tig + 4]);
                af[mt][3] = to_tf32(As[st][mb + g + 8][k8 + tig + 4]);
            }
            uint32_t bf[8][2];
#pragma unroll
            for (int nt = 0; nt < 8; nt++) {
                const int n = wn + nt * 8 + g;
                bf[nt][0] = to_tf32(Bs[st][k8 + tig][n]);
                bf[nt][1] = to_tf32(Bs[st][k8 + tig + 4][n]);
            }
#pragma unroll
            for (int mt = 0; mt < 2; mt++)
#pragma unroll
                for (int nt = 0; nt < 8; nt++)
                    mma_tf32(acc[mt][nt], af[mt], bf[nt]);
        }
        __syncthreads();
        st ^= 1;
    }

    // epilogue: D + bias -> C
#pragma unroll
    for (int nt = 0; nt < 8; nt++) {
        const int n = bn + wn + nt * 8 + 2 * tig;
        const float b0 = bias[n];
        const float b1 = bias[n + 1];
#pragma unroll
        for (int mt = 0; mt < 2; mt++) {
            const int m0 = bm + wm + mt * 16 + g;
            if (m0 < M) {
                float2 o = make_float2(acc[mt][nt][0] + b0, acc[mt][nt][1] + b1);
                *(float2*)&C[(size_t)m0 * N + n] = o;
            }
            const int m1 = m0 + 8;
            if (m1 < M) {
                float2 o = make_float2(acc[mt][nt][2] + b0, acc[mt][nt][3] + b1);
                *(float2*)&C[(size_t)m1 * N + n] = o;
            }
        }
    }
#undef FILL
}

// ---------------- softmax + bilinear sampling ----------------
__global__ __launch_bounds__(256) void sample_kernel(
    const float* __restrict__ refp,   // [BS,LQ,4,2]
    const float* __restrict__ off,    // [BS*LQ, 256] = [H][L][P][2]
    const float* __restrict__ logits, // [BS*LQ, 128] = [H][16]
    const float* __restrict__ v,      // [BS,LQ,8,32]
    float* __restrict__ out)          // [BS*LQ, 256]
{
    __shared__ int4   s_off[HEADS][16];
    __shared__ float4 s_w[HEADS][16];

    const int bq = blockIdx.x;
    const int b = bq / LQ;
    const int h = threadIdx.x >> 5;
    const int lane = threadIdx.x & 31;
    const int j = lane & 15;          // (level,point) index

    const float* lg = logits + (size_t)bq * 128 + h * 16;
    float logit = lg[j];
    float mx = logit;
#pragma unroll
    for (int k = 8; k >= 1; k >>= 1)
        mx = fmaxf(mx, __shfl_xor_sync(0xffffffffu, mx, k, 16));
    float e = __expf(logit - mx);
    float s = e;
#pragma unroll
    for (int k = 8; k >= 1; k >>= 1)
        s += __shfl_xor_sync(0xffffffffu, s, k, 16);
    const float aw = e / s;

    const int l = j >> 2;
    const int D = 96 >> l;
    const int start = 12288 - (12288 >> (2 * l));
    const float fD = (float)D;

    const float2 r2 = ((const float2*)(refp + (size_t)bq * 8))[l];
    const float2 o2 = ((const float2*)(off + (size_t)bq * 256 + h * 32))[j];

    const float gx = fmaf(r2.x, fD, o2.x) - 0.5f;
    const float gy = fmaf(r2.y, fD, o2.y) - 0.5f;
    const float x0f = floorf(gx);
    const float y0f = floorf(gy);
    const float wx = gx - x0f;
    const float wy = gy - y0f;
    const int x0 = (int)x0f, y0 = (int)y0f;
    const int x1 = x0 + 1, y1 = y0 + 1;

    const bool vx0 = (x0 >= 0) & (x0 < D);
    const bool vx1 = (x1 >= 0) & (x1 < D);
    const bool vy0 = (y0 >= 0) & (y0 < D);
    const bool vy1 = (y1 >= 0) & (y1 < D);

    int4 o4;
    float4 w4;
    o4.x = (vx0 & vy0) ? (start + y0 * D + x0) * 256 : 0;
    o4.y = (vx1 & vy0) ? (start + y0 * D + x1) * 256 : 0;
    o4.z = (vx0 & vy1) ? (start + y1 * D + x0) * 256 : 0;
    o4.w = (vx1 & vy1) ? (start + y1 * D + x1) * 256 : 0;
    w4.x = (vx0 & vy0) ? (1.f - wx) * (1.f - wy) * aw : 0.f;
    w4.y = (vx1 & vy0) ? wx * (1.f - wy) * aw : 0.f;
    w4.z = (vx0 & vy1) ? (1.f - wx) * wy * aw : 0.f;
    w4.w = (vx1 & vy1) ? wx * wy * aw : 0.f;

    if (lane < 16) {
        s_off[h][j] = o4;
        s_w[h][j] = w4;
    }
    __syncwarp();

    const float* __restrict__ vb = v + (size_t)b * LQ * 256 + h * 32 + lane;
    float acc = 0.f;
#pragma unroll
    for (int p = 0; p < 16; p++) {
        const int4 o = s_off[h][p];
        const float4 w = s_w[h][p];
        acc = fmaf(w.x, __ldg(vb + o.x), acc);
        acc = fmaf(w.y, __ldg(vb + o.y), acc);
        acc = fmaf(w.z, __ldg(vb + o.z), acc);
        acc = fmaf(w.w, __ldg(vb + o.w), acc);
    }
    out[(size_t)bq * 256 + h * 32 + lane] = acc;
}

// ---------------- launch ----------------
extern "C" void kernel_launch(void* const* d_in, const int* in_sizes, int n_in,
                              void* d_out, int out_size)
{
    const float* query = (const float*)d_in[0];
    const float* refp  = (const float*)d_in[1];
    const float* value = (const float*)d_in[2];
    // d_in[3] = value_spatial_shapes (static, hardcoded)
    const float* W_off  = (const float*)d_in[4];
    const float* b_off  = (const float*)d_in[5];
    const float* W_attn = (const float*)d_in[6];
    const float* b_attn = (const float*)d_in[7];
    const float* W_val  = (const float*)d_in[8];
    const float* b_val  = (const float*)d_in[9];
    const float* W_out  = (const float*)d_in[10];
    const float* b_out  = (const float*)d_in[11];
    float* out = (float*)d_out;

    float *pv, *poff, *pattn, *pacc;
    cudaGetSymbolAddress((void**)&pv, g_v);
    cudaGetSymbolAddress((void**)&poff, g_off);
    cudaGetSymbolAddress((void**)&pattn, g_attn);
    cudaGetSymbolAddress((void**)&pacc, g_acc);

    const int M = MTOT;
    dim3 blk(256);
    dim3 grid256(2, (M + 127) / 128);
    dim3 grid128(1, (M + 127) / 128);

    gemm_tf32_kernel<<<grid256, blk>>>(value, W_val, b_val, pv, M, 256, 256);
    gemm_tf32_kernel<<<grid256, blk>>>(query, W_off, b_off, poff, M, 256, 256);
    gemm_tf32_kernel<<<grid128, blk>>>(query, W_attn, b_attn, pattn, M, 128, 256);
    sample_kernel<<<M, blk>>>(refp, poff, pattn, pv, pacc);
    gemm_tf32_kernel<<<grid256, blk>>>(pacc, W_out, b_out, out, M, 256, 256);
}

// round 11
// speedup vs baseline: 1.3494x; 1.0001x over previous
#include <cuda_runtime.h>
#include <cstdint>
#include <math.h>

#define BS 4
#define LQ 12240
#define EMBED 256
#define HEADS 8
#define MTOT (BS * LQ)   // 48960

// ---------------- scratch (no cudaMalloc allowed) ----------------
__device__ float g_v[(size_t)MTOT * 256];     // projected value [b,Lv,H,32]
__device__ float g_off[(size_t)MTOT * 256];   // offsets [b,q,H,L,P,2]
__device__ float g_attn[(size_t)MTOT * 128];  // attn logits [b,q,H,16]
__device__ float g_acc[(size_t)MTOT * 256];   // sampled acc [b,q,H,32]

// ---------------- tf32 tensor-core GEMM, cp.async 3-stage pipeline --------
// C[M,N] = A[M,K] @ B[K,N] + bias.  K mult of 16, N mult of 128.
// Block tile 128x128, 8 warps as 4(M) x 2(N), warp 32x64 = 2x8 m16n8k8 tiles.
// smem holds raw fp32 (filled by cp.async); cvt to tf32 at fragment load.
// One __syncthreads per k-tile; fills run 2 tiles ahead.

__device__ __forceinline__ uint32_t to_tf32(float x) {
    uint32_t h;
    asm("cvt.rna.tf32.f32 %0, %1;" : "=r"(h) : "f"(x));
    return h;
}

__device__ __forceinline__ void mma_tf32(float* d, const uint32_t* a, const uint32_t* b) {
    asm volatile(
        "mma.sync.aligned.m16n8k8.row.col.f32.tf32.tf32.f32 "
        "{%0,%1,%2,%3}, {%4,%5,%6,%7}, {%8,%9}, {%0,%1,%2,%3};"
        : "+f"(d[0]), "+f"(d[1]), "+f"(d[2]), "+f"(d[3])
        : "r"(a[0]), "r"(a[1]), "r"(a[2]), "r"(a[3]), "r"(b[0]), "r"(b[1]));
}

__device__ __forceinline__ void cp_async16(void* smem, const void* gmem) {
    uint32_t s = (uint32_t)__cvta_generic_to_shared(smem);
    asm volatile("cp.async.ca.shared.global [%0], [%1], 16;" :: "r"(s), "l"(gmem));
}

#define ASTRIDE 20    // floats per A row (16 + 4 pad): bank = 20g+tig, conflict-free
#define BSTRIDE 136   // floats per B row (128 + 8 pad): bank = 8*tig+g, conflict-free

__global__ __launch_bounds__(256) void gemm_tf32_kernel(
    const float* __restrict__ A, const float* __restrict__ B,
    const float* __restrict__ bias, float* __restrict__ C,
    int M, int N, int K)
{
    __shared__ float As[3][128][ASTRIDE];
    __shared__ float Bs[3][16][BSTRIDE];

    const int tid = threadIdx.x;
    const int bm = blockIdx.y * 128;
    const int bn = blockIdx.x * 128;
    const int warp = tid >> 5;
    const int lane = tid & 31;
    const int wm = (warp >> 1) * 32;
    const int wn = (warp & 1) * 64;
    const int g = lane >> 2;           // 0..7
    const int tig = lane & 3;          // 0..3

    // A fill: thread copies 32B of row (tid>>1) at k-offset (tid&1)*8
    const int a_row = tid >> 1;
    const int a_half = tid & 1;
    int a_grow = bm + a_row; if (a_grow >= M) a_grow = M - 1;
    const float* Ag = A + (size_t)a_grow * K + a_half * 8;

    // B fill: thread copies 32B of tile-row (tid>>4) at col (tid&15)*8
    const int b_row = tid >> 4;          // 0..15
    const int b_col = (tid & 15) * 8;    // 0..120
    const float* Bg = B + (size_t)b_row * N + bn + b_col;

#define FILL(kt, st) do { \
        const float* ap = Ag + (kt) * 16; \
        cp_async16(&As[st][a_row][a_half * 8], ap); \
        cp_async16(&As[st][a_row][a_half * 8 + 4], ap + 4); \
        const float* bp = Bg + (size_t)(kt) * 16 * N; \
        cp_async16(&Bs[st][b_row][b_col], bp); \
        cp_async16(&Bs[st][b_row][b_col + 4], bp + 4); \
        asm volatile("cp.async.commit_group;"); \
    } while (0)

    float acc[2][8][4];
#pragma unroll
    for (int i = 0; i < 2; i++)
#pragma unroll
        for (int j = 0; j < 8; j++)
#pragma unroll
            for (int r = 0; r < 4; r++) acc[i][j][r] = 0.f;

    const int NT = K / 16;   // >= 2 for all our GEMMs (K=256 -> 16)
    FILL(0, 0);
    FILL(1, 1);

    int st = 0;
    for (int kt = 0; kt < NT; kt++) {
        if (kt + 1 < NT) {
            asm volatile("cp.async.wait_group 1;");
        } else {
            asm volatile("cp.async.wait_group 0;");
        }
        __syncthreads();   // fill(kt) visible to all; all done computing stage being refilled

        if (kt + 2 < NT) {
            int fs = st - 1; if (fs < 0) fs += 3;   // (kt+2) % 3
            FILL(kt + 2, fs);
        }

#pragma unroll
        for (int ks = 0; ks < 2; ks++) {
            const int k8 = ks * 8;
            uint32_t af[2][4];
#pragma unroll
            for (int mt = 0; mt < 2; mt++) {
                const int mb = wm + mt * 16;
                af[mt][0] = to_tf32(As[st][mb + g][k8 + tig]);
                af[mt][1] = to_tf32(As[st][mb + g + 8][k8 + tig]);
                af[mt][2] = to_tf32(As[st][mb + g][k8 + tig + 4]);
                af[mt][3] = to_tf32(As[st][mb + g + 8][k8 + tig + 4]);
            }
            uint32_t bf[8][2];
#pragma unroll
            for (int nt = 0; nt < 8; nt++) {
                const int n = wn + nt * 8 + g;
                bf[nt][0] = to_tf32(Bs[st][k8 + tig][n]);
                bf[nt][1] = to_tf32(Bs[st][k8 + tig + 4][n]);
            }
#pragma unroll
            for (int mt = 0; mt < 2; mt++)
#pragma unroll
                for (int nt = 0; nt < 8; nt++)
                    mma_tf32(acc[mt][nt], af[mt], bf[nt]);
        }

        st = st + 1 == 3 ? 0 : st + 1;
    }

    // epilogue: D + bias -> C
#pragma unroll
    for (int nt = 0; nt < 8; nt++) {
        const int n = bn + wn + nt * 8 + 2 * tig;
        const float b0 = bias[n];
        const float b1 = bias[n + 1];
#pragma unroll
        for (int mt = 0; mt < 2; mt++) {
            const int m0 = bm + wm + mt * 16 + g;
            if (m0 < M) {
                float2 o = make_float2(acc[mt][nt][0] + b0, acc[mt][nt][1] + b1);
                *(float2*)&C[(size_t)m0 * N + n] = o;
            }
            const int m1 = m0 + 8;
            if (m1 < M) {
                float2 o = make_float2(acc[mt][nt][2] + b0, acc[mt][nt][3] + b1);
                *(float2*)&C[(size_t)m1 * N + n] = o;
            }
        }
    }
#undef FILL
}

// ---------------- softmax + bilinear sampling ----------------
__global__ __launch_bounds__(256) void sample_kernel(
    const float* __restrict__ refp,   // [BS,LQ,4,2]
    const float* __restrict__ off,    // [BS*LQ, 256] = [H][L][P][2]
    const float* __restrict__ logits, // [BS*LQ, 128] = [H][16]
    const float* __restrict__ v,      // [BS,LQ,8,32]
    float* __restrict__ out)          // [BS*LQ, 256]
{
    __shared__ int4   s_off[HEADS][16];
    __shared__ float4 s_w[HEADS][16];

    const int bq = blockIdx.x;
    const int b = bq / LQ;
    const int h = threadIdx.x >> 5;
    const int lane = threadIdx.x & 31;
    const int j = lane & 15;          // (level,point) index

    const float* lg = logits + (size_t)bq * 128 + h * 16;
    float logit = lg[j];
    float mx = logit;
#pragma unroll
    for (int k = 8; k >= 1; k >>= 1)
        mx = fmaxf(mx, __shfl_xor_sync(0xffffffffu, mx, k, 16));
    float e = __expf(logit - mx);
    float s = e;
#pragma unroll
    for (int k = 8; k >= 1; k >>= 1)
        s += __shfl_xor_sync(0xffffffffu, s, k, 16);
    const float aw = e / s;

    const int l = j >> 2;
    const int D = 96 >> l;
    const int start = 12288 - (12288 >> (2 * l));
    const float fD = (float)D;

    const float2 r2 = ((const float2*)(refp + (size_t)bq * 8))[l];
    const float2 o2 = ((const float2*)(off + (size_t)bq * 256 + h * 32))[j];

    const float gx = fmaf(r2.x, fD, o2.x) - 0.5f;
    const float gy = fmaf(r2.y, fD, o2.y) - 0.5f;
    const float x0f = floorf(gx);
    const float y0f = floorf(gy);
    const float wx = gx - x0f;
    const float wy = gy - y0f;
    const int x0 = (int)x0f, y0 = (int)y0f;
    const int x1 = x0 + 1, y1 = y0 + 1;

    const bool vx0 = (x0 >= 0) & (x0 < D);
    const bool vx1 = (x1 >= 0) & (x1 < D);
    const bool vy0 = (y0 >= 0) & (y0 < D);
    const bool vy1 = (y1 >= 0) & (y1 < D);

    int4 o4;
    float4 w4;
    o4.x = (vx0 & vy0) ? (start + y0 * D + x0) * 256 : 0;
    o4.y = (vx1 & vy0) ? (start + y0 * D + x1) * 256 : 0;
    o4.z = (vx0 & vy1) ? (start + y1 * D + x0) * 256 : 0;
    o4.w = (vx1 & vy1) ? (start + y1 * D + x1) * 256 : 0;
    w4.x = (vx0 & vy0) ? (1.f - wx) * (1.f - wy) * aw : 0.f;
    w4.y = (vx1 & vy0) ? wx * (1.f - wy) * aw : 0.f;
    w4.z = (vx0 & vy1) ? (1.f - wx) * wy * aw : 0.f;
    w4.w = (vx1 & vy1) ? wx * wy * aw : 0.f;

    if (lane < 16) {
        s_off[h][j] = o4;
        s_w[h][j] = w4;
    }
    __syncwarp();

    const float* __restrict__ vb = v + (size_t)b * LQ * 256 + h * 32 + lane;
    float acc = 0.f;
#pragma unroll
    for (int p = 0; p < 16; p++) {
        const int4 o = s_off[h][p];
        const float4 w = s_w[h][p];
        acc = fmaf(w.x, __ldg(vb + o.x), acc);
        acc = fmaf(w.y, __ldg(vb + o.y), acc);
        acc = fmaf(w.z, __ldg(vb + o.z), acc);
        acc = fmaf(w.w, __ldg(vb + o.w), acc);
    }
    out[(size_t)bq * 256 + h * 32 + lane] = acc;
}

// ---------------- launch ----------------
extern "C" void kernel_launch(void* const* d_in, const int* in_sizes, int n_in,
                              void* d_out, int out_size)
{
    const float* query = (const float*)d_in[0];
    const float* refp  = (const float*)d_in[1];
    const float* value = (const float*)d_in[2];
    // d_in[3] = value_spatial_shapes (static, hardcoded)
    const float* W_off  = (const float*)d_in[4];
    const float* b_off  = (const float*)d_in[5];
    const float* W_attn = (const float*)d_in[6];
    const float* b_attn = (const float*)d_in[7];
    const float* W_val  = (const float*)d_in[8];
    const float* b_val  = (const float*)d_in[9];
    const float* W_out  = (const float*)d_in[10];
    const float* b_out  = (const float*)d_in[11];
    float* out = (float*)d_out;

    float *pv, *poff, *pattn, *pacc;
    cudaGetSymbolAddress((void**)&pv, g_v);
    cudaGetSymbolAddress((void**)&poff, g_off);
    cudaGetSymbolAddress((void**)&pattn, g_attn);
    cudaGetSymbolAddress((void**)&pacc, g_acc);

    const int M = MTOT;
    dim3 blk(256);
    dim3 grid256(2, (M + 127) / 128);
    dim3 grid128(1, (M + 127) / 128);

    gemm_tf32_kernel<<<grid256, blk>>>(value, W_val, b_val, pv, M, 256, 256);
    gemm_tf32_kernel<<<grid256, blk>>>(query, W_off, b_off, poff, M, 256, 256);
    gemm_tf32_kernel<<<grid128, blk>>>(query, W_attn, b_attn, pattn, M, 128, 256);
    sample_kernel<<<M, blk>>>(refp, poff, pattn, pv, pacc);
    gemm_tf32_kernel<<<grid256, blk>>>(pacc, W_out, b_out, out, M, 256, 256);
}

// round 12
// speedup vs baseline: 1.4245x; 1.0557x over previous
#include <cuda_runtime.h>
#include <cstdint>
#include <math.h>

#define BS 4
#define LQ 12240
#define EMBED 256
#define HEADS 8
#define MTOT (BS * LQ)   // 48960

// ---------------- scratch (no cudaMalloc allowed) ----------------
__device__ float g_v[(size_t)MTOT * 256];     // projected value [b,Lv,H,32]
__device__ float g_off[(size_t)MTOT * 256];   // offsets [b,q,H,L,P,2]
__device__ float g_attn[(size_t)MTOT * 128];  // attn logits [b,q,H,16]
__device__ float g_acc[(size_t)MTOT * 256];   // sampled acc [b,q,H,32]

// ---------------- tf32 tensor-core GEMM, cp.async 3-stage pipeline --------
// Block tile 128x128, 8 warps as 4(M) x 2(N), warp 32x64 = 2x8 m16n8k8 tiles.

__device__ __forceinline__ uint32_t to_tf32(float x) {
    uint32_t h;
    asm("cvt.rna.tf32.f32 %0, %1;" : "=r"(h) : "f"(x));
    return h;
}

__device__ __forceinline__ void mma_tf32(float* d, const uint32_t* a, const uint32_t* b) {
    asm volatile(
        "mma.sync.aligned.m16n8k8.row.col.f32.tf32.tf32.f32 "
        "{%0,%1,%2,%3}, {%4,%5,%6,%7}, {%8,%9}, {%0,%1,%2,%3};"
        : "+f"(d[0]), "+f"(d[1]), "+f"(d[2]), "+f"(d[3])
        : "r"(a[0]), "r"(a[1]), "r"(a[2]), "r"(a[3]), "r"(b[0]), "r"(b[1]));
}

__device__ __forceinline__ void cp_async16(void* smem, const void* gmem) {
    uint32_t s = (uint32_t)__cvta_generic_to_shared(smem);
    asm volatile("cp.async.ca.shared.global [%0], [%1], 16;" :: "r"(s), "l"(gmem));
}

#define ASTRIDE 20    // floats per A row (16 + 4 pad): conflict-free frag LDS
#define BSTRIDE 136   // floats per B row (128 + 8 pad): conflict-free frag LDS

// Shared GEMM body. Caller provides smem stages. All control uniform per CTA.
__device__ __forceinline__ void gemm_body(
    const float* __restrict__ A, const float* __restrict__ B,
    const float* __restrict__ bias, float* __restrict__ C,
    int M, int N, int K, int bm, int bn,
    float (*As)[128][ASTRIDE], float (*Bs)[16][BSTRIDE])
{
    const int tid = threadIdx.x;
    const int warp = tid >> 5;
    const int lane = tid & 31;
    const int wm = (warp >> 1) * 32;
    const int wn = (warp & 1) * 64;
    const int g = lane >> 2;           // 0..7
    const int tig = lane & 3;          // 0..3

    const int a_row = tid >> 1;
    const int a_half = tid & 1;
    int a_grow = bm + a_row; if (a_grow >= M) a_grow = M - 1;
    const float* Ag = A + (size_t)a_grow * K + a_half * 8;

    const int b_row = tid >> 4;          // 0..15
    const int b_col = (tid & 15) * 8;    // 0..120
    const float* Bg = B + (size_t)b_row * N + bn + b_col;

#define FILL(kt, st) do { \
        const float* ap = Ag + (kt) * 16; \
        cp_async16(&As[st][a_row][a_half * 8], ap); \
        cp_async16(&As[st][a_row][a_half * 8 + 4], ap + 4); \
        const float* bp = Bg + (size_t)(kt) * 16 * N; \
        cp_async16(&Bs[st][b_row][b_col], bp); \
        cp_async16(&Bs[st][b_row][b_col + 4], bp + 4); \
        asm volatile("cp.async.commit_group;"); \
    } while (0)

    float acc[2][8][4];
#pragma unroll
    for (int i = 0; i < 2; i++)
#pragma unroll
        for (int j = 0; j < 8; j++)
#pragma unroll
            for (int r = 0; r < 4; r++) acc[i][j][r] = 0.f;

    const int NT = K / 16;
    FILL(0, 0);
    FILL(1, 1);

    int st = 0;
    for (int kt = 0; kt < NT; kt++) {
        if (kt + 1 < NT) {
            asm volatile("cp.async.wait_group 1;");
        } else {
            asm volatile("cp.async.wait_group 0;");
        }
        __syncthreads();

        if (kt + 2 < NT) {
            int fs = st - 1; if (fs < 0) fs += 3;   // (kt+2) % 3
            FILL(kt + 2, fs);
        }

#pragma unroll
        for (int ks = 0; ks < 2; ks++) {
            const int k8 = ks * 8;
            uint32_t af[2][4];
#pragma unroll
            for (int mt = 0; mt < 2; mt++) {
                const int mb = wm + mt * 16;
                af[mt][0] = to_tf32(As[st][mb + g][k8 + tig]);
                af[mt][1] = to_tf32(As[st][mb + g + 8][k8 + tig]);
                af[mt][2] = to_tf32(As[st][mb + g][k8 + tig + 4]);
                af[mt][3] = to_tf32(As[st][mb + g + 8][k8 + tig + 4]);
            }
            uint32_t bf[8][2];
#pragma unroll
            for (int nt = 0; nt < 8; nt++) {
                const int n = wn + nt * 8 + g;
                bf[nt][0] = to_tf32(Bs[st][k8 + tig][n]);
                bf[nt][1] = to_tf32(Bs[st][k8 + tig + 4][n]);
            }
#pragma unroll
            for (int mt = 0; mt < 2; mt++)
#pragma unroll
                for (int nt = 0; nt < 8; nt++)
                    mma_tf32(acc[mt][nt], af[mt], bf[nt]);
        }

        st = st + 1 == 3 ? 0 : st + 1;
    }

#pragma unroll
    for (int nt = 0; nt < 8; nt++) {
        const int n = bn + wn + nt * 8 + 2 * tig;
        const float b0 = bias[n];
        const float b1 = bias[n + 1];
#pragma unroll
        for (int mt = 0; mt < 2; mt++) {
            const int m0 = bm + wm + mt * 16 + g;
            if (m0 < M) {
                float2 o = make_float2(acc[mt][nt][0] + b0, acc[mt][nt][1] + b1);
                *(float2*)&C[(size_t)m0 * N + n] = o;
            }
            const int m1 = m0 + 8;
            if (m1 < M) {
                float2 o = make_float2(acc[mt][nt][2] + b0, acc[mt][nt][3] + b1);
                *(float2*)&C[(size_t)m1 * N + n] = o;
            }
        }
    }
#undef FILL
}

// Standalone GEMM (used for the output projection).
__global__ __launch_bounds__(256) void gemm_tf32_kernel(
    const float* __restrict__ A, const float* __restrict__ B,
    const float* __restrict__ bias, float* __restrict__ C,
    int M, int N, int K)
{
    __shared__ float As[3][128][ASTRIDE];
    __shared__ float Bs[3][16][BSTRIDE];
    gemm_body(A, B, bias, C, M, N, K, blockIdx.y * 128, blockIdx.x * 128, As, Bs);
}

// Merged projection kernel: the three independent input GEMMs in one launch.
// blockIdx.x slot: 0-1 -> v = value@W_val (N=256); 2-3 -> off = query@W_off
// (N=256); 4 -> attn = query@W_attn (N=128).
__global__ __launch_bounds__(256) void proj_tf32_kernel(
    const float* __restrict__ query, const float* __restrict__ value,
    const float* __restrict__ W_val, const float* __restrict__ b_val,
    const float* __restrict__ W_off, const float* __restrict__ b_off,
    const float* __restrict__ W_attn, const float* __restrict__ b_attn,
    float* __restrict__ v_out, float* __restrict__ off_out,
    float* __restrict__ attn_out, int M, int K)
{
    __shared__ float As[3][128][ASTRIDE];
    __shared__ float Bs[3][16][BSTRIDE];

    const int slot = blockIdx.x;
    const float *A, *B, *bias;
    float* C;
    int N, bn;
    if (slot < 2)      { A = value; B = W_val;  bias = b_val;  C = v_out;    N = 256; bn = slot * 128; }
    else if (slot < 4) { A = query; B = W_off;  bias = b_off;  C = off_out;  N = 256; bn = (slot - 2) * 128; }
    else               { A = query; B = W_attn; bias = b_attn; C = attn_out; N = 128; bn = 0; }

    gemm_body(A, B, bias, C, M, N, K, blockIdx.y * 128, bn, As, Bs);
}

// ---------------- softmax + bilinear sampling ----------------
__global__ __launch_bounds__(256) void sample_kernel(
    const float* __restrict__ refp,   // [BS,LQ,4,2]
    const float* __restrict__ off,    // [BS*LQ, 256] = [H][L][P][2]
    const float* __restrict__ logits, // [BS*LQ, 128] = [H][16]
    const float* __restrict__ v,      // [BS,LQ,8,32]
    float* __restrict__ out)          // [BS*LQ, 256]
{
    __shared__ int4   s_off[HEADS][16];
    __shared__ float4 s_w[HEADS][16];

    const int bq = blockIdx.x;
    const int b = bq / LQ;
    const int h = threadIdx.x >> 5;
    const int lane = threadIdx.x & 31;
    const int j = lane & 15;          // (level,point) index

    const float* lg = logits + (size_t)bq * 128 + h * 16;
    float logit = lg[j];
    float mx = logit;
#pragma unroll
    for (int k = 8; k >= 1; k >>= 1)
        mx = fmaxf(mx, __shfl_xor_sync(0xffffffffu, mx, k, 16));
    float e = __expf(logit - mx);
    float s = e;
#pragma unroll
    for (int k = 8; k >= 1; k >>= 1)
        s += __shfl_xor_sync(0xffffffffu, s, k, 16);
    const float aw = e / s;

    const int l = j >> 2;
    const int D = 96 >> l;
    const int start = 12288 - (12288 >> (2 * l));
    const float fD = (float)D;

    const float2 r2 = ((const float2*)(refp + (size_t)bq * 8))[l];
    const float2 o2 = ((const float2*)(off + (size_t)bq * 256 + h * 32))[j];

    const float gx = fmaf(r2.x, fD, o2.x) - 0.5f;
    const float gy = fmaf(r2.y, fD, o2.y) - 0.5f;
    const float x0f = floorf(gx);
    const float y0f = floorf(gy);
    const float wx = gx - x0f;
    const float wy = gy - y0f;
    const int x0 = (int)x0f, y0 = (int)y0f;
    const int x1 = x0 + 1, y1 = y0 + 1;

    const bool vx0 = (x0 >= 0) & (x0 < D);
    const bool vx1 = (x1 >= 0) & (x1 < D);
    const bool vy0 = (y0 >= 0) & (y0 < D);
    const bool vy1 = (y1 >= 0) & (y1 < D);

    int4 o4;
    float4 w4;
    o4.x = (vx0 & vy0) ? (start + y0 * D + x0) * 256 : 0;
    o4.y = (vx1 & vy0) ? (start + y0 * D + x1) * 256 : 0;
    o4.z = (vx0 & vy1) ? (start + y1 * D + x0) * 256 : 0;
    o4.w = (vx1 & vy1) ? (start + y1 * D + x1) * 256 : 0;
    w4.x = (vx0 & vy0) ? (1.f - wx) * (1.f - wy) * aw : 0.f;
    w4.y = (vx1 & vy0) ? wx * (1.f - wy) * aw : 0.f;
    w4.z = (vx0 & vy1) ? (1.f - wx) * wy * aw : 0.f;
    w4.w = (vx1 & vy1) ? wx * wy * aw : 0.f;

    if (lane < 16) {
        s_off[h][j] = o4;
        s_w[h][j] = w4;
    }
    __syncwarp();

    const float* __restrict__ vb = v + (size_t)b * LQ * 256 + h * 32 + lane;
    float acc = 0.f;
#pragma unroll
    for (int p = 0; p < 16; p++) {
        const int4 o = s_off[h][p];
        const float4 w = s_w[h][p];
        acc = fmaf(w.x, __ldg(vb + o.x), acc);
        acc = fmaf(w.y, __ldg(vb + o.y), acc);
        acc = fmaf(w.z, __ldg(vb + o.z), acc);
        acc = fmaf(w.w, __ldg(vb + o.w), acc);
    }
    out[(size_t)bq * 256 + h * 32 + lane] = acc;
}

// ---------------- launch ----------------
extern "C" void kernel_launch(void* const* d_in, const int* in_sizes, int n_in,
                              void* d_out, int out_size)
{
    const float* query = (const float*)d_in[0];
    const float* refp  = (const float*)d_in[1];
    const float* value = (const float*)d_in[2];
    // d_in[3] = value_spatial_shapes (static, hardcoded)
    const float* W_off  = (const float*)d_in[4];
    const float* b_off  = (const float*)d_in[5];
    const float* W_attn = (const float*)d_in[6];
    const float* b_attn = (const float*)d_in[7];
    const float* W_val  = (const float*)d_in[8];
    const float* b_val  = (const float*)d_in[9];
    const float* W_out  = (const float*)d_in[10];
    const float* b_out  = (const float*)d_in[11];
    float* out = (float*)d_out;

    float *pv, *poff, *pattn, *pacc;
    cudaGetSymbolAddress((void**)&pv, g_v);
    cudaGetSymbolAddress((void**)&poff, g_off);
    cudaGetSymbolAddress((void**)&pattn, g_attn);
    cudaGetSymbolAddress((void**)&pacc, g_acc);

    const int M = MTOT;
    dim3 blk(256);
    dim3 gridProj(5, (M + 127) / 128);
    dim3 gridOut(2, (M + 127) / 128);

    proj_tf32_kernel<<<gridProj, blk>>>(query, value, W_val, b_val, W_off, b_off,
                                        W_attn, b_attn, pv, poff, pattn, M, 256);
    sample_kernel<<<M, blk>>>(refp, poff, pattn, pv, pacc);
    gemm_tf32_kernel<<<gridOut, blk>>>(pacc, W_out, b_out, out, M, 256, 256);
}